// round 3
// baseline (speedup 1.0000x reference)
#include <cuda_runtime.h>
#include <math.h>

#define N_NODES 50000
#define N_EDGES 200000

// ---------------- scratch (static __device__; no allocation allowed) ----------------
__device__ __align__(16) float g_h1 [(size_t)N_EDGES * 256];    // enn hidden 1
__device__ __align__(16) float g_big1[(size_t)N_EDGES * 1024];  // enn hidden 2
__device__ __align__(16) float g_big2[(size_t)N_EDGES * 1024];  // z = elu(h2@w3+b3)
__device__ __align__(16) float g_agg [N_NODES * 64];
__device__ __align__(16) float g_xcur[N_NODES * 64];
__device__ __align__(16) float g_xin [N_NODES * 64];
__device__ __align__(16) float g_hbuf[N_NODES * 64];
__device__ __align__(16) float g_gh1 [N_NODES * 256];
__device__ __align__(16) float g_gh2 [N_NODES * 256];

// scratch-id -> device-global pointer (resolved in device code)
__device__ __forceinline__ float* sbuf(int id) {
    switch (id) {
        case 1: return g_h1;
        case 2: return g_big1;
        case 3: return g_big2;
        case 4: return g_agg;
        case 5: return g_xcur;
        case 6: return g_xin;
        case 7: return g_hbuf;
        case 8: return g_gh1;
        case 9: return g_gh2;
    }
    return nullptr;
}

__device__ __forceinline__ float elu_f(float v) {
    return v > 0.f ? v : expm1f(v);
}

// ---------------- generic tiled GEMM: C = act(A@B + bias [+ D]) -----------------
// A: [M,K] row-major (Aid=0 -> Aext, else scratch), B: [K,N] row-major (external),
// bias: [N], D: [M,N] optional (Did), C: scratch (Cid)
// STORE4: also write v to out4[m*256 + n*4 + layer]  (valid when N == 64)
template<int BM, int BN, int BK, int TM, int TN, bool ELU_ACT, bool ADDD, bool STORE4>
__global__ __launch_bounds__(256, 2)
void gemm_k(int M, int N, int K,
            const float* __restrict__ Aext, int Aid,
            const float* __restrict__ B,
            const float* __restrict__ bias,
            int Did, int Cid,
            float* __restrict__ out4, int layer)
{
    const float* A = (Aid == 0) ? Aext : sbuf(Aid);
    const float* D = ADDD ? sbuf(Did) : nullptr;
    float*       C = sbuf(Cid);

    __shared__ float As[BK][BM];
    __shared__ float Bs[BK][BN];

    const int tid = threadIdx.x;
    constexpr int TW = BN / TN;               // threads along N
    const int tx = tid % TW;
    const int ty = tid / TW;
    const int m0 = blockIdx.y * BM;
    const int n0 = blockIdx.x * BN;

    float acc[TM][TN];
#pragma unroll
    for (int i = 0; i < TM; i++)
#pragma unroll
        for (int j = 0; j < TN; j++) acc[i][j] = 0.f;

    constexpr int A_ITERS = (BM * BK) / (256 * 4);
    constexpr int B_ITERS = (BK * BN) / (256 * 4);

    for (int kk = 0; kk < K; kk += BK) {
        // load A slab (transposed into As[k][m]), guard M boundary
#pragma unroll
        for (int it = 0; it < A_ITERS; ++it) {
            int i = tid * 4 + it * 1024;
            int r = i / BK;
            int c = i % BK;
            int m = m0 + r;
            float4 v;
            if (m < M) v = *(const float4*)(A + (size_t)m * K + kk + c);
            else       v = make_float4(0.f, 0.f, 0.f, 0.f);
            As[c + 0][r] = v.x;
            As[c + 1][r] = v.y;
            As[c + 2][r] = v.z;
            As[c + 3][r] = v.w;
        }
        // load B slab (row-major); callers guarantee N % BN == 0, K % BK == 0
#pragma unroll
        for (int it = 0; it < B_ITERS; ++it) {
            int i = tid * 4 + it * 1024;
            int r = i / BN;
            int c = i % BN;
            *(float4*)(&Bs[r][c]) = *(const float4*)(B + (size_t)(kk + r) * N + n0 + c);
        }
        __syncthreads();

#pragma unroll
        for (int k = 0; k < BK; k++) {
            float a[TM], b[TN];
#pragma unroll
            for (int i = 0; i < TM; i += 4)
                *(float4*)&a[i] = *(const float4*)&As[k][ty * TM + i];
#pragma unroll
            for (int j = 0; j < TN; j += 4)
                *(float4*)&b[j] = *(const float4*)&Bs[k][tx * TN + j];
#pragma unroll
            for (int i = 0; i < TM; i++)
#pragma unroll
                for (int j = 0; j < TN; j++)
                    acc[i][j] = fmaf(a[i], b[j], acc[i][j]);
        }
        __syncthreads();
    }

#pragma unroll
    for (int i = 0; i < TM; i++) {
        int m = m0 + ty * TM + i;
        if (m >= M) continue;
#pragma unroll
        for (int j = 0; j < TN; j++) {
            int n = n0 + tx * TN + j;
            float v = acc[i][j] + bias[n];
            if (ADDD) v += D[(size_t)m * N + n];
            if (ELU_ACT) v = elu_f(v);
            C[(size_t)m * N + n] = v;
            if (STORE4) out4[(size_t)m * 256 + n * 4 + layer] = v;
        }
    }
}

// ---------------- small helper kernels (reference globals directly) ----------------
__global__ void zero_agg_k() {
    int i = blockIdx.x * 256 + threadIdx.x;
    if (i < N_NODES * 64) g_agg[i] = 0.f;
}

// msg[e,o] = sum_i x[src,i] * z[e, i*64+o];  atomicAdd into agg[dst,o]
// edge_index is int32 (JAX downcasts int64 -> int32 without x64 mode).
__global__ void msg_scatter_k(const float* __restrict__ x,
                              const int* __restrict__ ei)
{
    int e = blockIdx.x;
    int o = threadIdx.x;  // 64 threads
    __shared__ float xs[16];
    int s = ei[e];
    int d = ei[N_EDGES + e];
    // defensive bounds guard: if dtype assumption is wrong we get a clean
    // rel_err signal instead of an address-space trap
    if (s < 0 || s >= N_NODES || d < 0 || d >= N_NODES) return;
    if (o < 16) xs[o] = x[(size_t)s * 16 + o];
    __syncthreads();
    float acc = 0.f;
    const float* zr = g_big2 + (size_t)e * 1024;
#pragma unroll
    for (int i = 0; i < 16; i++)
        acc = fmaf(xs[i], zr[i * 64 + o], acc);
    atomicAdd(&g_agg[d * 64 + o], acc);
}

// xin = hbuf = elu(xcur)
__global__ void elu_copy_k() {
    int i = blockIdx.x * 256 + threadIdx.x;
    if (i < N_NODES * 64) {
        float w = elu_f(g_xcur[i]);
        g_xin[i] = w;
        g_hbuf[i] = w;
    }
}

// hbuf[dst] += xin[src]   (segment_sum)
__global__ void gather_scatter_k(const int* __restrict__ ei) {
    int idx = blockIdx.x * 256 + threadIdx.x;   // E*64 = 12.8M fits int
    if (idx >= N_EDGES * 64) return;
    int e = idx >> 6;
    int o = idx & 63;
    int s = ei[e];
    int d = ei[N_EDGES + e];
    if (s < 0 || s >= N_NODES || d < 0 || d >= N_NODES) return;
    atomicAdd(&g_hbuf[d * 64 + o], g_xin[s * 64 + o]);
}

// ---------------- launch ----------------
static inline int cdiv(int a, int b) { return (a + b - 1) / b; }

extern "C" void kernel_launch(void* const* d_in, const int* in_sizes, int n_in,
                              void* d_out, int out_size)
{
    const float* x   = (const float*)d_in[0];
    const int*   ei  = (const int*)d_in[1];     // int32 (JAX default, no x64)
    const float* ea  = (const float*)d_in[2];
    const float* ew1 = (const float*)d_in[3];
    const float* eb1 = (const float*)d_in[4];
    const float* ew2 = (const float*)d_in[5];
    const float* eb2 = (const float*)d_in[6];
    const float* ew3 = (const float*)d_in[7];
    const float* eb3 = (const float*)d_in[8];
    const float* rw  = (const float*)d_in[9];
    const float* rb  = (const float*)d_in[10];
    const float* gw1 = (const float*)d_in[11];
    const float* gb1 = (const float*)d_in[12];
    const float* gw2 = (const float*)d_in[13];
    const float* gb2 = (const float*)d_in[14];
    const float* gw3 = (const float*)d_in[15];
    const float* gb3 = (const float*)d_in[16];
    float* out = (float*)d_out;

    // scratch ids: 1=h1 2=big1 3=big2 4=agg 5=xcur 7=hbuf 8=gh1 9=gh2

    // ---- Layer 0: NNConv ----
    // h1 = elu(edge_attr @ enn_w1 + b1)   [200000,16] @ [16,256]
    gemm_k<128,128,16,8,8, true,false,false>
        <<<dim3(2, cdiv(N_EDGES,128)), 256>>>(N_EDGES, 256, 16,
            ea, 0, ew1, eb1, 0, 1, nullptr, 0);
    // h2 = elu(h1 @ enn_w2 + b2)          [200000,256] @ [256,1024]
    gemm_k<128,128,16,8,8, true,false,false>
        <<<dim3(8, cdiv(N_EDGES,128)), 256>>>(N_EDGES, 1024, 256,
            nullptr, 1, ew2, eb2, 0, 2, nullptr, 0);
    // z = elu(h2 @ enn_w3 + b3)           [200000,1024] @ [1024,1024]
    gemm_k<128,128,16,8,8, true,false,false>
        <<<dim3(8, cdiv(N_EDGES,128)), 256>>>(N_EDGES, 1024, 1024,
            nullptr, 2, ew3, eb3, 0, 3, nullptr, 0);

    // agg = segment_sum(einsum(x[src], w_e), dst)
    zero_agg_k<<<cdiv(N_NODES*64, 256), 256>>>();
    msg_scatter_k<<<N_EDGES, 64>>>(x, ei);

    // xcur = x @ root_w + agg + root_b ; store out[:,:,0]
    gemm_k<128,64,16,8,4, false,true,true>
        <<<dim3(1, cdiv(N_NODES,128)), 256>>>(N_NODES, 64, 16,
            x, 0, rw, rb, 4, 5, out, 0);

    // ---- Layers 1..3: GINConv ----
    for (int l = 0; l < 3; l++) {
        elu_copy_k<<<cdiv(N_NODES*64, 256), 256>>>();
        gather_scatter_k<<<cdiv(N_EDGES*64, 256), 256>>>(ei);
        // gh1 = elu(hbuf @ gin_w1[l] + gb1[l])   [50000,64]@[64,256]
        gemm_k<128,128,16,8,8, true,false,false>
            <<<dim3(2, cdiv(N_NODES,128)), 256>>>(N_NODES, 256, 64,
                nullptr, 7, gw1 + (size_t)l*64*256, gb1 + l*256, 0, 8, nullptr, 0);
        // gh2 = elu(gh1 @ gin_w2[l] + gb2[l])    [50000,256]@[256,256]
        gemm_k<128,128,16,8,8, true,false,false>
            <<<dim3(2, cdiv(N_NODES,128)), 256>>>(N_NODES, 256, 256,
                nullptr, 8, gw2 + (size_t)l*256*256, gb2 + l*256, 0, 9, nullptr, 0);
        // xcur = gh2 @ gin_w3[l] + gb3[l] ; store out[:,:,l+1]
        gemm_k<128,64,16,8,4, false,false,true>
            <<<dim3(1, cdiv(N_NODES,128)), 256>>>(N_NODES, 64, 256,
                nullptr, 9, gw3 + (size_t)l*256*64, gb3 + l*64, 0, 5, out, l + 1);
    }
}